// round 3
// baseline (speedup 1.0000x reference)
#include <cuda_runtime.h>

#define NB 64
#define NP 1024
#define M1 128
#define M2 32

__device__ float g_bufA[(size_t)NB * 128 * M1 * 64];
__device__ float g_bufB[(size_t)NB * 128 * M1 * 64];
__device__ float g_f1[NB * 128 * M1];
__device__ float g_c1[NB * M1 * 3];
__device__ float g_c2[NB * M2 * 3];
__device__ int   g_i1[NB * M1];
__device__ int   g_i2[NB * M2];
__device__ int   g_n1[NB * M1 * 64];
__device__ int   g_n2[NB * M2 * 64];
__device__ float g_x3[NB * 259 * M2];
__device__ float g_z3a[NB * 512 * M2];
__device__ float g_z3b[NB * 256 * M2];
__device__ float g_xc[515 * NB];
__device__ float g_fa1[512 * NB];
__device__ float g_fa2[256 * NB];
__device__ float g_wt[350000];
__device__ float g_sum[512], g_sq[512], g_mean[512], g_rstd[512];

__global__ void tw_k(const float* W, float* Wt, int O, int C) {
    int i = blockIdx.x * 256 + threadIdx.x;
    if (i < O * C) { int o = i / C, c = i - o * C; Wt[c * O + o] = W[i]; }
}

template <int NT>
__global__ void fps_k(const float* pts, int sB, int sC, int sN, int ns,
                      float* ctr, int* idx) {
    __shared__ float sv[NT / 32]; __shared__ int si[NT / 32];
    __shared__ float sc[3]; __shared__ int sfar;
    int b = blockIdx.x, t = threadIdx.x;
    const float* p = pts + (size_t)b * sB;
    float px = p[t * sN], py = p[t * sN + sC], pz = p[t * sN + 2 * sC];
    float dist = 1e10f; int far = 0;
    for (int s = 0; s < ns; s++) {
        if (t == far) {
            sc[0] = px; sc[1] = py; sc[2] = pz; idx[b * ns + s] = far;
            float* cw = ctr + ((size_t)b * ns + s) * 3;
            cw[0] = px; cw[1] = py; cw[2] = pz;
        }
        __syncthreads();
        float dx = __fadd_rn(px, -sc[0]), dy = __fadd_rn(py, -sc[1]), dz = __fadd_rn(pz, -sc[2]);
        float d = __fadd_rn(__fadd_rn(__fmul_rn(dx, dx), __fmul_rn(dy, dy)), __fmul_rn(dz, dz));
        dist = fminf(dist, d);
        float v = dist; int ii = t;
        #pragma unroll
        for (int o = 16; o; o >>= 1) {
            float ov = __shfl_down_sync(0xffffffffu, v, o);
            int oi = __shfl_down_sync(0xffffffffu, ii, o);
            if (ov > v || (ov == v && oi < ii)) { v = ov; ii = oi; }
        }
        if ((t & 31) == 0) { sv[t >> 5] = v; si[t >> 5] = ii; }
        __syncthreads();
        if (t < 32) {
            const int nw = NT / 32;
            float v2 = (t < nw) ? sv[t] : -1.0f;
            int i2 = (t < nw) ? si[t] : 0x7fffffff;
            #pragma unroll
            for (int o = 16; o; o >>= 1) {
                float ov = __shfl_down_sync(0xffffffffu, v2, o);
                int oi = __shfl_down_sync(0xffffffffu, i2, o);
                if (ov > v2 || (ov == v2 && oi < i2)) { v2 = ov; i2 = oi; }
            }
            if (t == 0) sfar = i2;
        }
        __syncthreads();
        far = sfar;
    }
}

__global__ __launch_bounds__(128) void bq_k(const float* ctr, int Mc, const float* pts, int n,
                                            int sB, int sC, int sN, float r2, int* nidx) {
    __shared__ float sp[3 * NP];
    int b = blockIdx.x, t = threadIdx.x;
    for (int i = t; i < 3 * n; i += 128) {
        int c = i / n, j = i - c * n;
        sp[c * n + j] = pts[(size_t)b * sB + (size_t)j * sN + (size_t)c * sC];
    }
    __syncthreads();
    if (t < Mc) {
        const float* cr = ctr + ((size_t)b * Mc + t) * 3;
        float cx = cr[0], cy = cr[1], cz = cr[2];
        int base = (b * Mc + t) * 64, cnt = 0;
        for (int j = 0; j < n && cnt < 64; j++) {
            float dx = __fadd_rn(cx, -sp[j]), dy = __fadd_rn(cy, -sp[n + j]), dz = __fadd_rn(cz, -sp[2 * n + j]);
            float d = __fadd_rn(__fadd_rn(__fmul_rn(dx, dx), __fmul_rn(dy, dy)), __fmul_rn(dz, dz));
            if (d < r2) { nidx[base + cnt] = j; cnt++; }
        }
        int first = nidx[base];
        for (int c2 = cnt; c2 < 64; c2++) nidx[base + c2] = first;
    }
}

__global__ void rel1_k(const float* coords) {
    int bm = blockIdx.x, b = bm >> 7, m = bm & 127, k = threadIdx.x;
    int n = g_n1[bm * 64 + k];
    const float* cb = coords + (size_t)b * 3 * NP;
    const float* ct = &g_c1[((size_t)b * M1 + m) * 3];
    size_t base = (size_t)b * 3 * M1 * 64 + (size_t)m * 64 + k;
    g_bufB[base]                       = cb[n]          - ct[0];
    g_bufB[base + (size_t)M1 * 64]     = cb[NP + n]     - ct[1];
    g_bufB[base + (size_t)2 * M1 * 64] = cb[2 * NP + n] - ct[2];
}

__global__ __launch_bounds__(128) void bx2_k() {
    int bm = blockIdx.x, b = bm >> 5, m = bm & 31, tid = threadIdx.x;
    __shared__ int sn[64]; __shared__ float sc2[3];
    if (tid < 64) sn[tid] = g_n2[bm * 64 + tid];
    if (tid < 3) sc2[tid] = g_c2[((size_t)b * M2 + m) * 3 + tid];
    __syncthreads();
    for (int i = tid; i < 131 * 64; i += 128) {
        int c = i >> 6, k = i & 63, n = sn[k];
        float v;
        if (c < 3) v = g_c1[((size_t)b * M1 + n) * 3 + c] - sc2[c];
        else       v = g_f1[((size_t)b * 128 + (c - 3)) * M1 + n];
        g_bufB[(((size_t)b * 131 + c) * M2 + m) * 64 + k] = v;
    }
}

__global__ __launch_bounds__(256) void conv_k(const float* __restrict__ in,
                                              const float* __restrict__ wt,
                                              float* __restrict__ out,
                                              int Cin, int Cout, int M, int normIn) {
    extern __shared__ float s_in[];
    int bm = blockIdx.x, b = bm / M, m = bm - b * M;
    int tid = threadIdx.x, lane = tid & 31, wp = tid >> 5;
    size_t MK = (size_t)M * 64;
    const float* inb = in + (size_t)b * Cin * MK + (size_t)m * 64;
    for (int i = tid; i < Cin * 64; i += 256) {
        int c = i >> 6, k = i & 63;
        float v = inb[(size_t)c * MK + k];
        if (normIn) v = fmaxf((v - g_mean[c]) * g_rstd[c], 0.0f);
        s_in[i] = v;
    }
    __syncthreads();
    float* outb = out + (size_t)b * Cout * MK + (size_t)m * 64;
    for (int ob = wp * 4; ob < Cout; ob += 32) {
        float a00 = 0, a01 = 0, a10 = 0, a11 = 0, a20 = 0, a21 = 0, a30 = 0, a31 = 0;
        #pragma unroll 4
        for (int c = 0; c < Cin; c++) {
            float4 wv = *(const float4*)(wt + (size_t)c * Cout + ob);
            float x0 = s_in[(c << 6) + lane], x1 = s_in[(c << 6) + lane + 32];
            a00 += wv.x * x0; a01 += wv.x * x1;
            a10 += wv.y * x0; a11 += wv.y * x1;
            a20 += wv.z * x0; a21 += wv.z * x1;
            a30 += wv.w * x0; a31 += wv.w * x1;
        }
        outb[(size_t)(ob + 0) * MK + lane] = a00; outb[(size_t)(ob + 0) * MK + lane + 32] = a01;
        outb[(size_t)(ob + 1) * MK + lane] = a10; outb[(size_t)(ob + 1) * MK + lane + 32] = a11;
        outb[(size_t)(ob + 2) * MK + lane] = a20; outb[(size_t)(ob + 2) * MK + lane + 32] = a21;
        outb[(size_t)(ob + 3) * MK + lane] = a30; outb[(size_t)(ob + 3) * MK + lane + 32] = a31;
        float as[4] = { a00 + a01, a10 + a11, a20 + a21, a30 + a31 };
        float qs[4] = { a00 * a00 + a01 * a01, a10 * a10 + a11 * a11,
                        a20 * a20 + a21 * a21, a30 * a30 + a31 * a31 };
        #pragma unroll
        for (int j = 0; j < 4; j++) {
            float s = as[j], q = qs[j];
            #pragma unroll
            for (int o = 16; o; o >>= 1) {
                s += __shfl_down_sync(0xffffffffu, s, o);
                q += __shfl_down_sync(0xffffffffu, q, o);
            }
            if (lane == 0) { atomicAdd(&g_sum[ob + j], s); atomicAdd(&g_sq[ob + j], q); }
        }
    }
}

__global__ __launch_bounds__(256) void conv1_k(const float* __restrict__ in,
                                               const float* __restrict__ wt,
                                               float* __restrict__ out,
                                               int Cin, int Cout, int normIn) {
    extern __shared__ float s_in[];
    int b = blockIdx.x, tid = threadIdx.x, lane = tid & 31, wp = tid >> 5;
    const float* inb = in + (size_t)b * Cin * 32;
    for (int i = tid; i < Cin * 32; i += 256) {
        int c = i >> 5;
        float v = inb[i];
        if (normIn) v = fmaxf((v - g_mean[c]) * g_rstd[c], 0.0f);
        s_in[i] = v;
    }
    __syncthreads();
    float* outb = out + (size_t)b * Cout * 32;
    for (int ob = wp * 4; ob < Cout; ob += 32) {
        float a0 = 0, a1 = 0, a2 = 0, a3 = 0;
        #pragma unroll 4
        for (int c = 0; c < Cin; c++) {
            float4 wv = *(const float4*)(wt + (size_t)c * Cout + ob);
            float x = s_in[(c << 5) + lane];
            a0 += wv.x * x; a1 += wv.y * x; a2 += wv.z * x; a3 += wv.w * x;
        }
        float aa[4] = { a0, a1, a2, a3 };
        #pragma unroll
        for (int j = 0; j < 4; j++) {
            outb[(ob + j) * 32 + lane] = aa[j];
            float s = aa[j], q = aa[j] * aa[j];
            #pragma unroll
            for (int o = 16; o; o >>= 1) {
                s += __shfl_down_sync(0xffffffffu, s, o);
                q += __shfl_down_sync(0xffffffffu, q, o);
            }
            if (lane == 0) { atomicAdd(&g_sum[ob + j], s); atomicAdd(&g_sq[ob + j], q); }
        }
    }
}

__global__ void fin_k(int C, float invN) {
    int c = threadIdx.x;
    if (c < C) {
        float s = g_sum[c], q = g_sq[c];
        float mn = s * invN;
        g_mean[c] = mn;
        g_rstd[c] = rsqrtf(q * invN - mn * mn + 1e-5f);
    }
    g_sum[c] = 0.0f; g_sq[c] = 0.0f;
}

__global__ void maxp_k(const float* __restrict__ in, float* __restrict__ out,
                       int C, int M, int chOff, int outC) {
    int g = blockIdx.x * 8 + (threadIdx.x >> 5), lane = threadIdx.x & 31;
    const float* p = in + (size_t)g * 64;
    float v = fmaxf(p[lane], p[lane + 32]);
    #pragma unroll
    for (int o = 16; o; o >>= 1) v = fmaxf(v, __shfl_down_sync(0xffffffffu, v, o));
    if (lane == 0) {
        int m = g % M, c = (g / M) % C, b = g / (M * C);
        out[((size_t)(b * outC + chOff + c)) * M + m] =
            fmaxf((v - g_mean[c]) * g_rstd[c], 0.0f);
    }
}

__global__ void cc2_k() {
    int b = blockIdx.x, t = threadIdx.x;
    if (t < 96) {
        int c = t / 32, m = t % 32;
        g_x3[((size_t)(b * 259 + c)) * 32 + m] = g_c2[((size_t)b * 32 + m) * 3 + c];
    }
}

__global__ void mp3_k(const float* __restrict__ in, const float* __restrict__ oneh) {
    int b = blockIdx.x, o = threadIdx.x;
    const float* p = in + ((size_t)b * 512 + o) * 32;
    float v = p[0];
    #pragma unroll
    for (int m = 1; m < 32; m++) v = fmaxf(v, p[m]);
    g_xc[o * 64 + b] = fmaxf((v - g_mean[o]) * g_rstd[o], 0.0f);
    if (o < 3) g_xc[(512 + o) * 64 + b] = oneh[b * 3 + o];
}

__global__ void fc_k(const float* __restrict__ x, const float* __restrict__ w,
                     float* __restrict__ out, int Cin) {
    __shared__ float sm[2], sqv[2];
    int o = blockIdx.x, b = threadIdx.x;
    const float* wr = w + (size_t)o * Cin;
    float z = 0.0f;
    for (int c = 0; c < Cin; c++) z += x[c * 64 + b] * wr[c];
    float s = z, q = z * z;
    #pragma unroll
    for (int off = 16; off; off >>= 1) {
        s += __shfl_down_sync(0xffffffffu, s, off);
        q += __shfl_down_sync(0xffffffffu, q, off);
    }
    if ((b & 31) == 0) { sm[b >> 5] = s; sqv[b >> 5] = q; }
    __syncthreads();
    float mn = (sm[0] + sm[1]) * (1.0f / 64.0f);
    float vq = (sqv[0] + sqv[1]) * (1.0f / 64.0f);
    out[o * 64 + b] = fmaxf((z - mn) * rsqrtf(vq - mn * mn + 1e-5f), 0.0f);
}

__global__ void fco_k(const float* __restrict__ x, const float* __restrict__ w,
                      const float* __restrict__ bias, float* __restrict__ out) {
    int o = blockIdx.x, b = threadIdx.x;
    const float* wr = w + (size_t)o * 256;
    float z = bias[o];
    for (int c = 0; c < 256; c++) z += x[c * 64 + b] * wr[c];
    out[b * 59 + o] = z;
}

extern "C" void kernel_launch(void* const* d_in, const int* in_sizes, int n_in,
                              void* d_out, int out_size) {
    const float* coords = (const float*)d_in[0];
    const float* oneh   = (const float*)d_in[1];
    const float* w1a = (const float*)d_in[2];
    const float* w1b = (const float*)d_in[3];
    const float* w1c = (const float*)d_in[4];
    const float* w2a = (const float*)d_in[5];
    const float* w2b = (const float*)d_in[6];
    const float* w2c = (const float*)d_in[7];
    const float* w3a = (const float*)d_in[8];
    const float* w3b = (const float*)d_in[9];
    const float* w3c = (const float*)d_in[10];
    const float* wc1 = (const float*)d_in[11];
    const float* wc2 = (const float*)d_in[12];
    const float* wc3 = (const float*)d_in[13];
    const float* bc3 = (const float*)d_in[14];

    float *bufA, *bufB, *wt, *f1, *c1, *c2, *x3, *z3a, *z3b, *xc, *fa1, *fa2;
    int *i1, *i2, *n1, *n2;
    cudaGetSymbolAddress((void**)&bufA, g_bufA);
    cudaGetSymbolAddress((void**)&bufB, g_bufB);
    cudaGetSymbolAddress((void**)&wt, g_wt);
    cudaGetSymbolAddress((void**)&f1, g_f1);
    cudaGetSymbolAddress((void**)&c1, g_c1);
    cudaGetSymbolAddress((void**)&c2, g_c2);
    cudaGetSymbolAddress((void**)&x3, g_x3);
    cudaGetSymbolAddress((void**)&z3a, g_z3a);
    cudaGetSymbolAddress((void**)&z3b, g_z3b);
    cudaGetSymbolAddress((void**)&xc, g_xc);
    cudaGetSymbolAddress((void**)&fa1, g_fa1);
    cudaGetSymbolAddress((void**)&fa2, g_fa2);
    cudaGetSymbolAddress((void**)&i1, g_i1);
    cudaGetSymbolAddress((void**)&i2, g_i2);
    cudaGetSymbolAddress((void**)&n1, g_n1);
    cudaGetSymbolAddress((void**)&n2, g_n2);

    // transpose conv weights into g_wt (Cin-major)
    tw_k<<<1, 256>>>(w1a, wt + 0, 64, 3);
    tw_k<<<16, 256>>>(w1b, wt + 192, 64, 64);
    tw_k<<<32, 256>>>(w1c, wt + 4288, 128, 64);
    tw_k<<<66, 256>>>(w2a, wt + 12480, 128, 131);
    tw_k<<<64, 256>>>(w2b, wt + 29248, 128, 128);
    tw_k<<<128, 256>>>(w2c, wt + 45632, 256, 128);
    tw_k<<<260, 256>>>(w3a, wt + 78400, 256, 259);
    tw_k<<<256, 256>>>(w3b, wt + 144704, 256, 256);
    tw_k<<<512, 256>>>(w3c, wt + 210240, 512, 256);

    // sampling / grouping
    fps_k<1024><<<NB, 1024>>>(coords, 3 * NP, NP, 1, 128, c1, i1);
    bq_k<<<NB, 128>>>(c1, 128, coords, 1024, 3 * NP, NP, 1, (float)(0.2 * 0.2), n1);
    fps_k<128><<<NB, 128>>>(c1, M1 * 3, 1, 3, 32, c2, i2);
    bq_k<<<NB, 128>>>(c2, 32, c1, 128, M1 * 3, 1, 3, (float)(0.4 * 0.4), n2);
    rel1_k<<<NB * M1, 64>>>(coords);

    // stage 1 shared MLP
    conv_k<<<NB * M1, 256, 3 * 256>>>(bufB, wt + 0, bufA, 3, 64, M1, 0);
    fin_k<<<1, 512>>>(64, 1.0f / 524288.0f);
    conv_k<<<NB * M1, 256, 64 * 256>>>(bufA, wt + 192, bufB, 64, 64, M1, 1);
    fin_k<<<1, 512>>>(64, 1.0f / 524288.0f);
    conv_k<<<NB * M1, 256, 64 * 256>>>(bufB, wt + 4288, bufA, 64, 128, M1, 1);
    fin_k<<<1, 512>>>(128, 1.0f / 524288.0f);
    maxp_k<<<NB * 128 * M1 / 8, 256>>>(bufA, f1, 128, M1, 0, 128);

    // stage 2
    bx2_k<<<NB * M2, 128>>>();
    conv_k<<<NB * M2, 256, 131 * 256>>>(bufB, wt + 12480, bufA, 131, 128, M2, 0);
    fin_k<<<1, 512>>>(128, 1.0f / 131072.0f);
    conv_k<<<NB * M2, 256, 128 * 256>>>(bufA, wt + 29248, bufB, 128, 128, M2, 1);
    fin_k<<<1, 512>>>(128, 1.0f / 131072.0f);
    conv_k<<<NB * M2, 256, 128 * 256>>>(bufB, wt + 45632, bufA, 128, 256, M2, 1);
    fin_k<<<1, 512>>>(256, 1.0f / 131072.0f);
    maxp_k<<<NB * 256 * M2 / 8, 256>>>(bufA, x3, 256, M2, 3, 259);
    cc2_k<<<NB, 96>>>();

    // stage 3 1D convs
    conv1_k<<<NB, 256, 259 * 128>>>(x3, wt + 78400, z3b, 259, 256, 0);
    fin_k<<<1, 512>>>(256, 1.0f / 2048.0f);
    conv1_k<<<NB, 256, 256 * 128>>>(z3b, wt + 144704, z3a, 256, 256, 1);
    fin_k<<<1, 512>>>(256, 1.0f / 2048.0f);
    conv1_k<<<NB, 256, 256 * 128>>>(z3a, wt + 210240, bufA, 256, 512, 1);
    fin_k<<<1, 512>>>(512, 1.0f / 2048.0f);
    mp3_k<<<NB, 512>>>(bufA, oneh);

    // FC head
    fc_k<<<512, 64>>>(xc, wc1, fa1, 515);
    fc_k<<<256, 64>>>(fa1, wc2, fa2, 512);
    fco_k<<<59, 64>>>(fa2, wc3, bc3, (float*)d_out);
}